// round 6
// baseline (speedup 1.0000x reference)
#include <cuda_runtime.h>
#include <cstdint>

// Problem constants (fixed shapes for this problem instance)
#define BB   16
#define FF   80
#define TXX  384
#define TYY  1728
#define OUTW 256

#define NEGF (-1e9f)
#define GCONST (-73.51508265637381f)   // -0.5*log(2*pi)*80

// Output layout (flattened concat of reference return tuple)
#define MU_Y_ELEMS   ((size_t)BB * FF * OUTW)                  // 327680
#define ATTN_ELEMS   ((size_t)BB * TXX * TYY)                  // 10616832
#define OFF_MU_Y     ((size_t)0)
#define OFF_ATTN     (MU_Y_ELEMS)
#define OFF_MELS     (OFF_ATTN + ATTN_ELEMS)                   // 10944512
#define OFF_MASK     (OFF_MELS + MU_Y_ELEMS)                   // 11272192

// Scratch (device globals: allocation-free rule)
__device__ float g_lp[(size_t)BB * TYY * TXX];   // [b][y][x]  ~42.5 MB
__device__ float g_msq[BB * TYY];
__device__ float g_xsq[BB * TXX];
__device__ int   g_pathidx[BB * TYY];

// ---------------------------------------------------------------------------
// Zero-fill the attn region of d_out (poisoned by harness)
// ---------------------------------------------------------------------------
__global__ void fill_attn_kernel(float* __restrict__ attn) {
    float4 z = make_float4(0.f, 0.f, 0.f, 0.f);
    float4* p = (float4*)attn;
    size_t n4 = ATTN_ELEMS / 4;
    for (size_t i = (size_t)blockIdx.x * blockDim.x + threadIdx.x;
         i < n4; i += (size_t)gridDim.x * blockDim.x)
        p[i] = z;
}

// ---------------------------------------------------------------------------
// Squared norms: g_msq[b][y] = -0.5*sum_f mel^2, g_xsq[b][x] = -0.5*sum_f mu^2
// ---------------------------------------------------------------------------
__global__ void sq_kernel(const float* __restrict__ mel,
                          const float* __restrict__ mu) {
    int i = blockIdx.x * blockDim.x + threadIdx.x;
    if (i < BB * TYY) {
        int b = i / TYY, y = i - b * TYY;
        const float* p = mel + (size_t)b * FF * TYY + y;
        float s = 0.f;
        #pragma unroll 8
        for (int f = 0; f < FF; ++f) {
            float v = p[(size_t)f * TYY];
            s += v * v;
        }
        g_msq[i] = -0.5f * s;
    } else {
        int j = i - BB * TYY;
        if (j < BB * TXX) {
            int b = j / TXX, x = j - b * TXX;
            const float* p = mu + (size_t)b * FF * TXX + x;
            float s = 0.f;
            #pragma unroll 8
            for (int f = 0; f < FF; ++f) {
                float v = p[(size_t)f * TXX];
                s += v * v;
            }
            g_xsq[j] = -0.5f * s;
        }
    }
}

// ---------------------------------------------------------------------------
// log-prior GEMM: g_lp[b][y][x] = sum_f mu[b,f,x]*mel[b,f,y] + msq[y] + xsq[x] + C
//                 masked to NEG outside (x < t_x && y < t_y)
// 64x64 tile, 256 threads, 4x4 micro-tile, K chunks of 16.
// ---------------------------------------------------------------------------
__global__ void lp_gemm_kernel(const float* __restrict__ mu,
                               const float* __restrict__ mel,
                               const int* __restrict__ tl,
                               const int* __restrict__ ml) {
    int b  = blockIdx.z;
    int x0 = blockIdx.x * 64;
    int y0 = blockIdx.y * 64;
    int t  = threadIdx.x;
    int txq = t & 15;       // x micro-tile index
    int tyq = t >> 4;       // y micro-tile index
    int txl = tl[b];
    int tyl = ml[b];

    float* out = g_lp + ((size_t)b * TYY + y0) * TXX + x0;

    if (x0 >= txl || y0 >= tyl) {
        // fully masked tile
        float4 n4 = make_float4(NEGF, NEGF, NEGF, NEGF);
        #pragma unroll
        for (int iy = 0; iy < 4; ++iy)
            *(float4*)(out + (size_t)(tyq * 4 + iy) * TXX + txq * 4) = n4;
        return;
    }

    __shared__ float As[16][64];   // [k][x]
    __shared__ float Bs[16][64];   // [k][y]

    float acc[4][4];
    #pragma unroll
    for (int i = 0; i < 4; ++i)
        #pragma unroll
        for (int j = 0; j < 4; ++j) acc[i][j] = 0.f;

    int lk  = t >> 4;          // 0..15 (k row)
    int lx4 = (t & 15) * 4;    // 0..60

    const float* mub  = mu  + (size_t)b * FF * TXX;
    const float* melb = mel + (size_t)b * FF * TYY;

    for (int k0 = 0; k0 < FF; k0 += 16) {
        *(float4*)&As[lk][lx4] = *(const float4*)(mub  + (size_t)(k0 + lk) * TXX + x0 + lx4);
        *(float4*)&Bs[lk][lx4] = *(const float4*)(melb + (size_t)(k0 + lk) * TYY + y0 + lx4);
        __syncthreads();
        #pragma unroll
        for (int k = 0; k < 16; ++k) {
            float a[4], bv[4];
            *(float4*)a  = *(float4*)&As[k][txq * 4];
            *(float4*)bv = *(float4*)&Bs[k][tyq * 4];
            #pragma unroll
            for (int iy = 0; iy < 4; ++iy)
                #pragma unroll
                for (int ix = 0; ix < 4; ++ix)
                    acc[iy][ix] += bv[iy] * a[ix];
        }
        __syncthreads();
    }

    float xs[4], ys[4];
    #pragma unroll
    for (int ix = 0; ix < 4; ++ix) xs[ix] = g_xsq[b * TXX + x0 + txq * 4 + ix];
    #pragma unroll
    for (int iy = 0; iy < 4; ++iy) ys[iy] = g_msq[b * TYY + y0 + tyq * 4 + iy];

    #pragma unroll
    for (int iy = 0; iy < 4; ++iy) {
        int y = y0 + tyq * 4 + iy;
        bool yok = (y < tyl);
        float r[4];
        #pragma unroll
        for (int ix = 0; ix < 4; ++ix) {
            int x = x0 + txq * 4 + ix;
            float val = acc[iy][ix] + xs[ix] + ys[iy] + GCONST;
            r[ix] = (yok && x < txl) ? val : NEGF;
        }
        *(float4*)(out + (size_t)(tyq * 4 + iy) * TXX + txq * 4) = *(float4*)r;
    }
}

// ---------------------------------------------------------------------------
// Monotonic alignment search: forward DP + backtrack.
// One warp per batch. Lane L owns x in [12L, 12L+12). v kept in registers.
// Comparison bits (for backtrack) stored in shared: cmp[y][lane] uint16 (12 bits).
// Register prefetch ring of 8 columns hides L2 latency.
// ---------------------------------------------------------------------------
__global__ void dp_kernel(const int* __restrict__ tl,
                          const int* __restrict__ ml,
                          float* __restrict__ attn_out) {
    extern __shared__ unsigned short cmpbuf[];   // [TYY][32]
    int b    = blockIdx.x;
    int lane = threadIdx.x;
    int txl  = tl[b];
    int tyl  = ml[b];

    const float* lp = g_lp + (size_t)b * TYY * TXX;
    const float4* lp4 = (const float4*)lp;       // column y at lp4 + y*(TXX/4)

    float v[12];
    #pragma unroll
    for (int i = 0; i < 12; ++i) v[i] = NEGF;
    if (lane == 0) v[0] = 0.f;

    float4 buf[8][3];
    #pragma unroll
    for (int p = 0; p < 8; ++p) {
        const float4* cp = lp4 + (size_t)p * (TXX / 4) + lane * 3;
        buf[p][0] = cp[0]; buf[p][1] = cp[1]; buf[p][2] = cp[2];
    }

    for (int yb = 0; yb < TYY; yb += 8) {
        #pragma unroll
        for (int p = 0; p < 8; ++p) {
            int y = yb + p;
            float c[12];
            c[0] = buf[p][0].x; c[1]  = buf[p][0].y; c[2]  = buf[p][0].z; c[3]  = buf[p][0].w;
            c[4] = buf[p][1].x; c[5]  = buf[p][1].y; c[6]  = buf[p][1].z; c[7]  = buf[p][1].w;
            c[8] = buf[p][2].x; c[9]  = buf[p][2].y; c[10] = buf[p][2].z; c[11] = buf[p][2].w;

            int yn = y + 8;
            if (yn < TYY) {
                const float4* cp = lp4 + (size_t)yn * (TXX / 4) + lane * 3;
                buf[p][0] = cp[0]; buf[p][1] = cp[1]; buf[p][2] = cp[2];
            }

            float prev = __shfl_up_sync(0xffffffffu, v[11], 1);
            if (lane == 0) prev = NEGF;

            unsigned m = 0;
            // descending: v[i] update reads only v[i-1] (still old value)
            #pragma unroll
            for (int i = 11; i >= 0; --i) {
                float left = (i == 0) ? prev : v[i - 1];
                bool cb = (v[i] < left);
                if (i == 0) cb = cb && (lane != 0);   // x==0: vprev[max(-1,0)]=vprev[0]
                m |= ((unsigned)cb) << i;
                v[i] = c[i] + fmaxf(v[i], left);
            }
            cmpbuf[y * 32 + lane] = (unsigned short)m;
        }
    }

    __syncwarp();

    if (lane == 0) {
        int idx = txl - 1;
        float* attn_b = attn_out + (size_t)b * TXX * TYY;
        for (int y = TYY - 1; y >= 0; --y) {
            g_pathidx[b * TYY + y] = idx;
            if (y < tyl) {
                attn_b[(size_t)idx * TYY + y] = 1.0f;
                if (idx > 0 && y > 0) {
                    int L = idx / 12;
                    int bit = idx - L * 12;
                    unsigned w = cmpbuf[y * 32 + L];
                    bool move = (idx == y) || ((w >> bit) & 1u);
                    if (move) --idx;
                }
            }
        }
    }
}

// ---------------------------------------------------------------------------
// Cut: y_cut_mask, mels_cut, mu_y (gather via path index)
// ---------------------------------------------------------------------------
__global__ void cut_kernel(const float* __restrict__ mel,
                           const float* __restrict__ mu,
                           const int* __restrict__ ml,
                           float* __restrict__ out) {
    int b = blockIdx.x;
    int j = threadIdx.x;   // 0..255
    int tyl = ml[b];
    int moff = tyl - OUTW; if (moff < 0) moff = 0;
    int off = moff >> 1;
    int cutlen = tyl < OUTW ? tyl : OUTW;
    bool act = (j < cutlen);
    float mask = act ? 1.f : 0.f;

    out[OFF_MASK + (size_t)b * OUTW + j] = mask;

    int xi = act ? g_pathidx[b * TYY + off + j] : 0;

    const float* melb = mel + (size_t)b * FF * TYY;
    const float* mub  = mu  + (size_t)b * FF * TXX;
    float* mels_cut = out + OFF_MELS + (size_t)b * FF * OUTW;
    float* mu_y     = out + OFF_MU_Y + (size_t)b * FF * OUTW;

    #pragma unroll 4
    for (int f = 0; f < FF; ++f) {
        float mv = act ? melb[(size_t)f * TYY + off + j] : 0.f;
        mels_cut[(size_t)f * OUTW + j] = mv;
        float uv = act ? mub[(size_t)f * TXX + xi] : 0.f;
        mu_y[(size_t)f * OUTW + j] = uv;
    }
}

// ---------------------------------------------------------------------------
extern "C" void kernel_launch(void* const* d_in, const int* in_sizes, int n_in,
                              void* d_out, int out_size) {
    const float* mu  = (const float*)d_in[0];   // [16,80,384]
    const float* mel = (const float*)d_in[1];   // [16,80,1728]
    const int*   tl  = (const int*)d_in[2];     // [16]
    const int*   ml  = (const int*)d_in[3];     // [16]
    float* out = (float*)d_out;

    fill_attn_kernel<<<2048, 256>>>(out + OFF_ATTN);

    sq_kernel<<<(BB * TYY + BB * TXX + 255) / 256, 256>>>(mel, mu);

    dim3 g(TXX / 64, TYY / 64, BB);
    lp_gemm_kernel<<<g, 256>>>(mu, mel, tl, ml);

    cudaFuncSetAttribute(dp_kernel, cudaFuncAttributeMaxDynamicSharedMemorySize,
                         TYY * 32 * (int)sizeof(unsigned short));
    dp_kernel<<<BB, 32, TYY * 32 * (int)sizeof(unsigned short)>>>(tl, ml, out + OFF_ATTN);

    cut_kernel<<<BB, OUTW>>>(mel, mu, ml, out);
}

// round 10
// speedup vs baseline: 1.7903x; 1.7903x over previous
#include <cuda_runtime.h>
#include <cstdint>

// Problem constants (fixed shapes for this problem instance)
#define BB   16
#define FF   80
#define TXX  384
#define TYY  1728
#define OUTW 256

#define NEGF (-1e9f)
#define GCONST (-73.51508265637381f)   // -0.5*log(2*pi)*80

// Output layout (flattened concat of reference return tuple)
#define MU_Y_ELEMS   ((size_t)BB * FF * OUTW)                  // 327680
#define ATTN_ELEMS   ((size_t)BB * TXX * TYY)                  // 10616832
#define OFF_MU_Y     ((size_t)0)
#define OFF_ATTN     (MU_Y_ELEMS)
#define OFF_MELS     (OFF_ATTN + ATTN_ELEMS)                   // 10944512
#define OFF_MASK     (OFF_MELS + MU_Y_ELEMS)                   // 11272192

// Scratch (device globals: allocation-free rule)
__device__ float g_lp[(size_t)BB * TYY * TXX];   // [b][y][x]  ~42.5 MB
__device__ float g_msq[BB * TYY];
__device__ float g_xsq[BB * TXX];
__device__ int   g_pathidx[BB * TYY];

// ---------------------------------------------------------------------------
// Zero-fill the attn region of d_out (poisoned by harness)
// ---------------------------------------------------------------------------
__global__ void fill_attn_kernel(float* __restrict__ attn) {
    float4 z = make_float4(0.f, 0.f, 0.f, 0.f);
    float4* p = (float4*)attn;
    size_t n4 = ATTN_ELEMS / 4;
    for (size_t i = (size_t)blockIdx.x * blockDim.x + threadIdx.x;
         i < n4; i += (size_t)gridDim.x * blockDim.x)
        p[i] = z;
}

// ---------------------------------------------------------------------------
// Squared norms: g_msq[b][y] = -0.5*sum_f mel^2, g_xsq[b][x] = -0.5*sum_f mu^2
// ---------------------------------------------------------------------------
__global__ void sq_kernel(const float* __restrict__ mel,
                          const float* __restrict__ mu) {
    int i = blockIdx.x * blockDim.x + threadIdx.x;
    if (i < BB * TYY) {
        int b = i / TYY, y = i - b * TYY;
        const float* p = mel + (size_t)b * FF * TYY + y;
        float s = 0.f;
        #pragma unroll 8
        for (int f = 0; f < FF; ++f) {
            float v = p[(size_t)f * TYY];
            s += v * v;
        }
        g_msq[i] = -0.5f * s;
    } else {
        int j = i - BB * TYY;
        if (j < BB * TXX) {
            int b = j / TXX, x = j - b * TXX;
            const float* p = mu + (size_t)b * FF * TXX + x;
            float s = 0.f;
            #pragma unroll 8
            for (int f = 0; f < FF; ++f) {
                float v = p[(size_t)f * TXX];
                s += v * v;
            }
            g_xsq[j] = -0.5f * s;
        }
    }
}

// ---------------------------------------------------------------------------
// log-prior GEMM: g_lp[b][y][x] = sum_f mu[b,f,x]*mel[b,f,y] + msq[y] + xsq[x] + C
//                 masked to NEG outside (x < t_x && y < t_y)
// Tiles with y0 >= t_y are never read by the DP (it stops at t_y) -> skipped.
// ---------------------------------------------------------------------------
__global__ void lp_gemm_kernel(const float* __restrict__ mu,
                               const float* __restrict__ mel,
                               const int* __restrict__ tl,
                               const int* __restrict__ ml) {
    int b  = blockIdx.z;
    int x0 = blockIdx.x * 64;
    int y0 = blockIdx.y * 64;
    int t  = threadIdx.x;
    int txq = t & 15;       // x micro-tile index
    int tyq = t >> 4;       // y micro-tile index
    int txl = tl[b];
    int tyl = ml[b];

    if (y0 >= tyl) return;   // never read downstream

    float* out = g_lp + ((size_t)b * TYY + y0) * TXX + x0;

    if (x0 >= txl) {
        // fully x-masked tile (still read by DP: must be NEG)
        float4 n4 = make_float4(NEGF, NEGF, NEGF, NEGF);
        #pragma unroll
        for (int iy = 0; iy < 4; ++iy)
            *(float4*)(out + (size_t)(tyq * 4 + iy) * TXX + txq * 4) = n4;
        return;
    }

    __shared__ float As[16][64];   // [k][x]
    __shared__ float Bs[16][64];   // [k][y]

    float acc[4][4];
    #pragma unroll
    for (int i = 0; i < 4; ++i)
        #pragma unroll
        for (int j = 0; j < 4; ++j) acc[i][j] = 0.f;

    int lk  = t >> 4;          // 0..15 (k row)
    int lx4 = (t & 15) * 4;    // 0..60

    const float* mub  = mu  + (size_t)b * FF * TXX;
    const float* melb = mel + (size_t)b * FF * TYY;

    for (int k0 = 0; k0 < FF; k0 += 16) {
        *(float4*)&As[lk][lx4] = *(const float4*)(mub  + (size_t)(k0 + lk) * TXX + x0 + lx4);
        *(float4*)&Bs[lk][lx4] = *(const float4*)(melb + (size_t)(k0 + lk) * TYY + y0 + lx4);
        __syncthreads();
        #pragma unroll
        for (int k = 0; k < 16; ++k) {
            float a[4], bv[4];
            *(float4*)a  = *(float4*)&As[k][txq * 4];
            *(float4*)bv = *(float4*)&Bs[k][tyq * 4];
            #pragma unroll
            for (int iy = 0; iy < 4; ++iy)
                #pragma unroll
                for (int ix = 0; ix < 4; ++ix)
                    acc[iy][ix] += bv[iy] * a[ix];
        }
        __syncthreads();
    }

    float xs[4], ys[4];
    #pragma unroll
    for (int ix = 0; ix < 4; ++ix) xs[ix] = g_xsq[b * TXX + x0 + txq * 4 + ix];
    #pragma unroll
    for (int iy = 0; iy < 4; ++iy) ys[iy] = g_msq[b * TYY + y0 + tyq * 4 + iy];

    #pragma unroll
    for (int iy = 0; iy < 4; ++iy) {
        int y = y0 + tyq * 4 + iy;
        bool yok = (y < tyl);
        float r[4];
        #pragma unroll
        for (int ix = 0; ix < 4; ++ix) {
            int x = x0 + txq * 4 + ix;
            float val = acc[iy][ix] + xs[ix] + ys[iy] + GCONST;
            r[ix] = (yok && x < txl) ? val : NEGF;
        }
        *(float4*)(out + (size_t)(tyq * 4 + iy) * TXX + txq * 4) = *(float4*)r;
    }
}

// ---------------------------------------------------------------------------
// Monotonic alignment search: warp-specialized producer/consumer.
//   warp 0      : forward DP (lane L owns x in [12L,12L+12)) + backtrack
//   warps 1..8  : cp.async lp columns (chunks of 8) into a SMEM ring
// Comparison bits for backtrack in shared: cmp[y][lane] uint16 (12 bits).
// DP stops at y = t_y (columns beyond are NEG and never read downstream).
// ---------------------------------------------------------------------------
#define CHUNK    8
#define NCHUNKS  6
#define RINGC    (CHUNK * NCHUNKS)                 // 48 columns
#define RING_BYTES ((size_t)RINGC * TXX * 4)       // 73728
#define CMP_BYTES  ((size_t)TYY * 32 * 2)          // 110592
#define DP_SMEM    (RING_BYTES + CMP_BYTES + 128)

__global__ __launch_bounds__(288, 1)
void dp_kernel(const int* __restrict__ tl,
               const int* __restrict__ ml,
               float* __restrict__ attn_out) {
    extern __shared__ char smem[];
    float* ring = (float*)smem;
    unsigned short* cmpb = (unsigned short*)(smem + RING_BYTES);
    volatile int* prod_flag = (volatile int*)(smem + RING_BYTES + CMP_BYTES);
    volatile int* cons_cnt  = (volatile int*)(smem + RING_BYTES + CMP_BYTES + NCHUNKS * 4);

    int b    = blockIdx.x;
    int t    = threadIdx.x;
    int wid  = t >> 5;
    int lane = t & 31;
    int txl  = tl[b];
    int tyl  = ml[b];
    int NC   = (tyl + CHUNK - 1) / CHUNK;

    const float* lp = g_lp + (size_t)b * TYY * TXX;

    if (t < NCHUNKS) prod_flag[t] = -1;
    if (t == 31)     *cons_cnt = 0;
    __syncthreads();

    if (wid >= 1) {
        // ---------------- producers ----------------
        unsigned ring_u32 = (unsigned)__cvta_generic_to_shared(ring);
        for (int cg = wid - 1; cg < NC; cg += 8) {
            if (cg >= NCHUNKS) {
                int need = cg - NCHUNKS + 1;
                while (*cons_cnt < need) __nanosleep(200);
            }
            int slot = cg % NCHUNKS;
            int ncol = tyl - cg * CHUNK; if (ncol > CHUNK) ncol = CHUNK;
            const char* src = (const char*)(lp + (size_t)cg * CHUNK * TXX);
            unsigned dst = ring_u32 + (unsigned)(slot * (CHUNK * TXX * 4));
            int nbytes = ncol * TXX * 4;   // contiguous columns
            for (int off = lane * 16; off < nbytes; off += 32 * 16) {
                asm volatile("cp.async.cg.shared.global [%0], [%1], 16;\n"
                             :: "r"(dst + (unsigned)off), "l"(src + off));
            }
            asm volatile("cp.async.commit_group;\n" ::: "memory");
            asm volatile("cp.async.wait_group 0;\n" ::: "memory");
            __syncwarp();
            __threadfence_block();
            if (lane == 0) prod_flag[slot] = cg;
        }
        return;
    }

    // ---------------- consumer (warp 0): forward DP ----------------
    float v[12];
    #pragma unroll
    for (int i = 0; i < 12; ++i) v[i] = NEGF;
    if (lane == 0) v[0] = 0.f;

    for (int cg = 0; cg < NC; ++cg) {
        int slot = cg % NCHUNKS;
        while (prod_flag[slot] != cg) { /* spin */ }
        __threadfence_block();
        int ncol = tyl - cg * CHUNK; if (ncol > CHUNK) ncol = CHUNK;
        const float4* colbase = (const float4*)(ring + (size_t)slot * CHUNK * TXX);
        int y0 = cg * CHUNK;

        #pragma unroll
        for (int p = 0; p < CHUNK; ++p) {
            if (p >= ncol) break;
            const float4* cp = colbase + p * (TXX / 4) + lane * 3;
            float4 b0 = cp[0], b1 = cp[1], b2 = cp[2];
            float c[12];
            c[0] = b0.x; c[1]  = b0.y; c[2]  = b0.z; c[3]  = b0.w;
            c[4] = b1.x; c[5]  = b1.y; c[6]  = b1.z; c[7]  = b1.w;
            c[8] = b2.x; c[9]  = b2.y; c[10] = b2.z; c[11] = b2.w;

            float prev = __shfl_up_sync(0xffffffffu, v[11], 1);
            if (lane == 0) prev = NEGF;

            unsigned m = 0;
            // descending: v[i] update reads only OLD v[i-1]
            #pragma unroll
            for (int i = 11; i >= 0; --i) {
                float left = (i == 0) ? prev : v[i - 1];
                bool cb = (v[i] < left);
                if (i == 0) cb = cb && (lane != 0);   // x==0: vprev[max(-1,0)]=vprev[0]
                m |= ((unsigned)cb) << i;
                v[i] = c[i] + fmaxf(v[i], left);
            }
            cmpb[(y0 + p) * 32 + lane] = (unsigned short)m;
        }

        __syncwarp();
        __threadfence_block();
        if (lane == 0) *cons_cnt = cg + 1;
    }

    __syncwarp();

    // ---------------- backtrack (lane 0) ----------------
    if (lane == 0) {
        int idx = txl - 1;
        float* attn_b = attn_out + (size_t)b * TXX * TYY;
        for (int y = tyl - 1; y > 0; --y) {
            g_pathidx[b * TYY + y] = idx;
            attn_b[(size_t)idx * TYY + y] = 1.0f;
            if (idx > 0) {
                int L = idx / 12;
                int bit = idx - L * 12;
                unsigned w = cmpb[y * 32 + L];
                bool move = (idx == y) || ((w >> bit) & 1u);
                if (move) --idx;
            }
        }
        g_pathidx[b * TYY] = idx;
        attn_b[(size_t)idx * TYY] = 1.0f;
    }
}

// ---------------------------------------------------------------------------
// Cut: y_cut_mask, mels_cut, mu_y (gather via path index)
// ---------------------------------------------------------------------------
__global__ void cut_kernel(const float* __restrict__ mel,
                           const float* __restrict__ mu,
                           const int* __restrict__ ml,
                           float* __restrict__ out) {
    int b = blockIdx.x;
    int j = threadIdx.x;   // 0..255
    int tyl = ml[b];
    int moff = tyl - OUTW; if (moff < 0) moff = 0;
    int off = moff >> 1;
    int cutlen = tyl < OUTW ? tyl : OUTW;
    bool act = (j < cutlen);
    float mask = act ? 1.f : 0.f;

    out[OFF_MASK + (size_t)b * OUTW + j] = mask;

    int xi = act ? g_pathidx[b * TYY + off + j] : 0;

    const float* melb = mel + (size_t)b * FF * TYY;
    const float* mub  = mu  + (size_t)b * FF * TXX;
    float* mels_cut = out + OFF_MELS + (size_t)b * FF * OUTW;
    float* mu_y     = out + OFF_MU_Y + (size_t)b * FF * OUTW;

    #pragma unroll 4
    for (int f = 0; f < FF; ++f) {
        float mv = act ? melb[(size_t)f * TYY + off + j] : 0.f;
        mels_cut[(size_t)f * OUTW + j] = mv;
        float uv = act ? mub[(size_t)f * TXX + xi] : 0.f;
        mu_y[(size_t)f * OUTW + j] = uv;
    }
}

// ---------------------------------------------------------------------------
extern "C" void kernel_launch(void* const* d_in, const int* in_sizes, int n_in,
                              void* d_out, int out_size) {
    const float* mu  = (const float*)d_in[0];   // [16,80,384]
    const float* mel = (const float*)d_in[1];   // [16,80,1728]
    const int*   tl  = (const int*)d_in[2];     // [16]
    const int*   ml  = (const int*)d_in[3];     // [16]
    float* out = (float*)d_out;

    fill_attn_kernel<<<2048, 256>>>(out + OFF_ATTN);

    sq_kernel<<<(BB * TYY + BB * TXX + 255) / 256, 256>>>(mel, mu);

    dim3 g(TXX / 64, TYY / 64, BB);
    lp_gemm_kernel<<<g, 256>>>(mu, mel, tl, ml);

    static int smem_set = 0;
    if (!smem_set) {
        cudaFuncSetAttribute(dp_kernel, cudaFuncAttributeMaxDynamicSharedMemorySize,
                             (int)DP_SMEM);
        smem_set = 1;
    }
    dp_kernel<<<BB, 288, DP_SMEM>>>(tl, ml, out + OFF_ATTN);

    cut_kernel<<<BB, OUTW>>>(mel, mu, ml, out);
}